// round 10
// baseline (speedup 1.0000x reference)
#include <cuda_runtime.h>

#define T_OBS 8
#define T_PRE 12
#define BATCH 524288
#define INP 2
#define H 8
#define EMB 16

typedef unsigned long long u64;

// ---------------- packed f32x2 + fast activation helpers (sm_103a) ----------------
__device__ __forceinline__ u64 fma2(u64 a, u64 b, u64 c) {
    u64 d; asm("fma.rn.f32x2 %0, %1, %2, %3;" : "=l"(d) : "l"(a), "l"(b), "l"(c)); return d;
}
__device__ __forceinline__ u64 pack2(float lo, float hi) {
    u64 d; asm("mov.b64 %0, {%1, %2};" : "=l"(d) : "f"(lo), "f"(hi)); return d;
}
__device__ __forceinline__ void unpack2(u64 v, float& lo, float& hi) {
    asm("mov.b64 {%0, %1}, %2;" : "=f"(lo), "=f"(hi) : "l"(v));
}
__device__ __forceinline__ float tanh_ap(float x) {
    float y; asm("tanh.approx.f32 %0, %1;" : "=f"(y) : "f"(x)); return y;
}

// Folded, gate-paired, sigmoid-prescaled weights, TWO pre-permuted copies.
//   pair0 = gates (i, f): both lanes prescaled by 0.5  (sigmoid = 0.5 + 0.5*tanh)
//   pair1 = gates (g, o): lane lo (g) unscaled, lane hi (o) prescaled by 0.5
// Copy hc (hc = thread half, 0 or 1) permutes the recurrent entries so that
// wh'[m] = wh[m ^ (4*hc)] — matching thread-relative hd order [own0..3, partner0..3].
// Row layout per (unit,pair): 6 ulonglong2:
//   v0=(A0,A1) v1=(b,wh'0) v2=(wh'1,wh'2) v3=(wh'3,wh'4) v4=(wh'5,wh'6) v5=(wh'7,pad)
__device__ float      g_rows[2][32][11];
__device__ ulonglong2 g_W2[2][2][H][2][6];   // [half][phase][unit][pair][6]

__global__ void prep_kernel(const float* __restrict__ W_in, const float* __restrict__ b_in,
                            const float* __restrict__ W_ih_obs, const float* __restrict__ W_hh_obs,
                            const float* __restrict__ b_ih_obs, const float* __restrict__ b_hh_obs,
                            const float* __restrict__ W_ih_pre, const float* __restrict__ W_hh_pre,
                            const float* __restrict__ b_ih_pre, const float* __restrict__ b_hh_pre) {
    int j = threadIdx.x;   // gate row 0..31
    int p = threadIdx.y;   // phase
    const float* W_ih = p ? W_ih_pre : W_ih_obs;
    const float* W_hh = p ? W_hh_pre : W_hh_obs;
    const float* b_ih = p ? b_ih_pre : b_ih_obs;
    const float* b_hh = p ? b_hh_pre : b_hh_obs;

    // fold embedding: A = W_ih @ W_in (32x2), b_tot = W_ih@b_in + b_ih + b_hh
    float a0 = 0.f, a1 = 0.f, bb = 0.f;
#pragma unroll
    for (int e = 0; e < EMB; e++) {
        float w = W_ih[j * EMB + e];
        a0 = fmaf(w, W_in[e * INP + 0], a0);
        a1 = fmaf(w, W_in[e * INP + 1], a1);
        bb = fmaf(w, b_in[e], bb);
    }
    bb += b_ih[j] + b_hh[j];

    // sigmoid gates (i: rows 0..7, f: 8..15, o: 24..31) prescaled by 0.5
    float s = (j < 16 || j >= 24) ? 0.5f : 1.0f;
    g_rows[p][j][0] = a0 * s;
    g_rows[p][j][1] = a1 * s;
    g_rows[p][j][2] = bb * s;
#pragma unroll
    for (int m = 0; m < H; m++)
        g_rows[p][j][3 + m] = W_hh[j * H + m] * s;

    __syncthreads();

    if (j < 16) {
        int k  = j % H;       // unit
        int pr = j / H;       // pair
        int rlo = pr ? (16 + k) : k;        // pair0: i ; pair1: g
        int rhi = pr ? (24 + k) : (8 + k);  // pair0: f ; pair1: o
#pragma unroll
        for (int hc = 0; hc < 2; hc++) {
            u64 vals[12];
            vals[0] = pack2(g_rows[p][rlo][0], g_rows[p][rhi][0]);
            vals[1] = pack2(g_rows[p][rlo][1], g_rows[p][rhi][1]);
            vals[2] = pack2(g_rows[p][rlo][2], g_rows[p][rhi][2]);
#pragma unroll
            for (int m = 0; m < H; m++) {
                int mp = m ^ (hc * 4);   // permuted recurrent index
                vals[3 + m] = pack2(g_rows[p][rlo][3 + mp], g_rows[p][rhi][3 + mp]);
            }
            vals[11] = 0ull;
#pragma unroll
            for (int m = 0; m < 6; m++) {
                ulonglong2 v; v.x = vals[2 * m]; v.y = vals[2 * m + 1];
                g_W2[hc][p][k][pr][m] = v;
            }
        }
    }
}

// one gate-pair accumulation: 10 fma2, weights loaded just-in-time
__device__ __forceinline__ u64 gp(const ulonglong2* __restrict__ Wr,
                                  u64 x0, u64 x1, const u64 hd[H]) {
    ulonglong2 v0 = Wr[0];
    ulonglong2 v1 = Wr[1];
    u64 a = fma2(v0.x, x0, v1.x);
    a = fma2(v0.y, x1, a);
    a = fma2(v1.y, hd[0], a);
    ulonglong2 v2 = Wr[2];
    a = fma2(v2.x, hd[1], a);
    a = fma2(v2.y, hd[2], a);
    ulonglong2 v3 = Wr[3];
    a = fma2(v3.x, hd[3], a);
    a = fma2(v3.y, hd[4], a);
    ulonglong2 v4 = Wr[4];
    a = fma2(v4.x, hd[5], a);
    a = fma2(v4.y, hd[6], a);
    ulonglong2 v5 = Wr[5];
    a = fma2(v5.x, hd[7], a);
    return a;
}

// activations for one unit (prescaled rows): acc0=(i/2, f/2), acc1=(g, o/2)
__device__ __forceinline__ float unit_act(u64 acc0, u64 acc1, float& c) {
    float gi, gf, gg, go;
    unpack2(acc0, gi, gf);
    unpack2(acc1, gg, go);
    float si = fmaf(0.5f, tanh_ap(gi), 0.5f);
    float sf = fmaf(0.5f, tanh_ap(gf), 0.5f);
    float gv = tanh_ap(gg);
    float so = fmaf(0.5f, tanh_ap(go), 0.5f);
    float cn = fmaf(sf, c, si * gv);
    c = cn;
    return so * tanh_ap(cn);
}

// Half-element scan: this thread owns 4 units (global base..base+3).
// hd is thread-relative: [0..3] = own units, [4..7] = partner units.
template <int T>
__device__ __forceinline__ void lstm_scan(const float* __restrict__ xin, int e, int base,
                                          const ulonglong2 (*__restrict__ W)[2][6],
                                          u64 hd[H], float c[4]) {
    float2 xv = *(const float2*)(xin + (size_t)e * INP);
#pragma unroll 1
    for (int t = 0; t < T; t++) {
        u64 x0 = pack2(xv.x, xv.x);
        u64 x1 = pack2(xv.y, xv.y);
        if (t + 1 < T)
            xv = *(const float2*)(xin + ((size_t)(t + 1) * BATCH + e) * INP);

        float hn[4];
#pragma unroll
        for (int kl = 0; kl < 4; kl++) {
            const ulonglong2 (*Wk)[6] = W[base + kl];
            u64 acc0 = gp(Wk[0], x0, x1, hd);  // (i, f), prescaled
            u64 acc1 = gp(Wk[1], x0, x1, hd);  // (g, o), o prescaled
            hn[kl] = unit_act(acc0, acc1, c[kl]);
            asm volatile("" ::: "memory");     // pin this unit's LDS to its body
        }
        // exchange with partner thread (lane ^ 1): 4 shuffles
#pragma unroll
        for (int kl = 0; kl < 4; kl++) {
            float pv = __shfl_xor_sync(0xffffffffu, hn[kl], 1);
            hd[kl]     = pack2(hn[kl], hn[kl]);
            hd[4 + kl] = pack2(pv, pv);
        }
    }
}

__global__ __launch_bounds__(256, 3) void lstm_kernel(
    const float* __restrict__ obs, const float* __restrict__ pre,
    const float* __restrict__ h0, const float* __restrict__ c0,
    const float* __restrict__ c0p, float* __restrict__ out)
{
    __shared__ ulonglong2 sW[2][2][H][2][6];
    {
        const u64* src = (const u64*)g_W2;
        u64* dst = (u64*)sW;
        constexpr int N = (int)(sizeof(g_W2) / sizeof(u64));   // 768
        for (int i = threadIdx.x; i < N; i += 256) dst[i] = src[i];
    }
    __syncthreads();

    const int tid  = blockIdx.x * 256 + threadIdx.x;
    const int e    = tid >> 1;           // batch element
    const int half = tid & 1;            // which 4-unit half this thread owns
    const int base = half * 4;           // global unit base

    // thread-relative hd: [0..3] own units (base..base+3), [4..7] partner units
    u64 hd[H];
    float c[4];
    {
        float4 own  = *(const float4*)(h0 + (size_t)e * H + base);
        float4 part = *(const float4*)(h0 + (size_t)e * H + (base ^ 4));
        hd[0] = pack2(own.x, own.x);  hd[1] = pack2(own.y, own.y);
        hd[2] = pack2(own.z, own.z);  hd[3] = pack2(own.w, own.w);
        hd[4] = pack2(part.x, part.x); hd[5] = pack2(part.y, part.y);
        hd[6] = pack2(part.z, part.z); hd[7] = pack2(part.w, part.w);
        float4 cv = *(const float4*)(c0 + (size_t)e * H + base);
        c[0] = cv.x; c[1] = cv.y; c[2] = cv.z; c[3] = cv.w;
    }

    // Phase 1: observation scan (weight copy pre-permuted for this half)
    lstm_scan<T_OBS>(obs, e, base, sW[half][0], hd, c);

    // c_out: out[j*B + e] = h[j]; this thread stores its 4 units
#pragma unroll
    for (int kl = 0; kl < 4; kl++) {
        float lo, hi; unpack2(hd[kl], lo, hi);
        out[(size_t)(base + kl) * BATCH + e] = lo;
    }

    // Phase 2: cell state reset to c0_pre, h carries over
    {
        float4 cv = *(const float4*)(c0p + (size_t)e * H + base);
        c[0] = cv.x; c[1] = cv.y; c[2] = cv.z; c[3] = cv.w;
    }
    lstm_scan<T_PRE>(pre, e, base, sW[half][1], hd, c);

#pragma unroll
    for (int kl = 0; kl < 4; kl++) {
        float lo, hi; unpack2(hd[kl], lo, hi);
        out[(size_t)(H + base + kl) * BATCH + e] = lo;
    }
}

extern "C" void kernel_launch(void* const* d_in, const int* in_sizes, int n_in,
                              void* d_out, int out_size) {
    const float* obs  = (const float*)d_in[0];
    const float* pre  = (const float*)d_in[1];
    const float* h0   = (const float*)d_in[2];
    const float* c0   = (const float*)d_in[3];
    const float* c0p  = (const float*)d_in[4];

    prep_kernel<<<1, dim3(32, 2)>>>(
        (const float*)d_in[5],  (const float*)d_in[6],
        (const float*)d_in[7],  (const float*)d_in[8],
        (const float*)d_in[9],  (const float*)d_in[10],
        (const float*)d_in[11], (const float*)d_in[12],
        (const float*)d_in[13], (const float*)d_in[14]);

    // two threads per batch element
    lstm_kernel<<<(BATCH * 2) / 256, 256>>>(obs, pre, h0, c0, c0p, (float*)d_out);
}